// round 17
// baseline (speedup 1.0000x reference)
#include <cuda_runtime.h>
#include <cstdint>

#define DIMS   1000
#define NLEV   10
#define NPIX   784
#define NBATCH 256
#define NCLS   10
#define PW     25      // 784 pixels -> 25 x u32 words
#define PWP    28      // g_posb row stride in words (112B)

// ---------------- device scratch (no allocations allowed) ----------------
__device__ uint32_t g_posb[1024 * PWP];   // packed position sign bits, d-major rows
__device__ uint32_t g_sigp[512];          // two 10-bit vt signatures per word
__device__ uint32_t g_tposp[512];         // two int16 tpos values per word

__device__ __forceinline__ uint32_t smem_u32(const void* p) {
    uint32_t a;
    asm("{ .reg .u64 t; cvta.to.shared.u64 t, %1; cvt.u32.u64 %0, t; }"
        : "=r"(a) : "l"(p));
    return a;
}

// ---------------- kernel A: pack position sign bits via cp.async.bulk ----
__global__ __launch_bounds__(256) void pack_kernel(const float* __restrict__ position,
                                                   float* __restrict__ out) {
    __shared__ __align__(128) float buf[8 * DIMS];        // 32000 B
    __shared__ __align__(8) unsigned long long mbar;

    const int w   = blockIdx.x;            // 0..24
    const int qq  = blockIdx.y;            // 0..3
    const int tid = threadIdx.x;
    const int p0  = w * 32 + qq * 8;       // first pixel of this byte
    const bool active = (p0 < NPIX);       // 784 = 98*8

    if (active) {
        uint32_t mb = smem_u32(&mbar);
        if (tid == 0) {
            asm volatile("mbarrier.init.shared.b64 [%0], %1;"
                         :: "r"(mb), "r"(1) : "memory");
        }
        __syncthreads();
        if (tid == 0) {
            const uint32_t bytes = 8 * DIMS * 4;   // 32000
            asm volatile("mbarrier.arrive.expect_tx.shared.b64 _, [%0], %1;"
                         :: "r"(mb), "r"(bytes) : "memory");
            asm volatile(
                "cp.async.bulk.shared::cluster.global.mbarrier::complete_tx::bytes "
                "[%0], [%1], %2, [%3];"
                :: "r"(smem_u32(buf)),
                   "l"(position + (size_t)p0 * DIMS),
                   "r"(bytes), "r"(mb) : "memory");
        }
        uint32_t mb2 = smem_u32(&mbar);
        uint32_t done;
        asm volatile(
            "{\n\t.reg .pred p;\n\t"
            "mbarrier.try_wait.parity.acquire.cta.shared::cta.b64 p, [%1], 0;\n\t"
            "selp.b32 %0, 1, 0, p;\n\t}"
            : "=r"(done) : "r"(mb2) : "memory");
        while (!done) {
            asm volatile(
                "{\n\t.reg .pred p;\n\t"
                "mbarrier.try_wait.parity.acquire.cta.shared::cta.b64 p, [%1], 0, 0x989680;\n\t"
                "selp.b32 %0, 1, 0, p;\n\t}"
                : "=r"(done) : "r"(mb2) : "memory");
        }
    }

    if (tid < 250) {
        const int d0 = tid * 4;
        uint32_t b0 = 0, b1 = 0, b2 = 0, b3 = 0;
        if (active) {
#pragma unroll
            for (int j = 0; j < 8; j++) {
                float4 v = ((const float4*)buf)[j * 250 + tid];
                b0 |= (v.x > 0.0f ? 1u : 0u) << j;
                b1 |= (v.y > 0.0f ? 1u : 0u) << j;
                b2 |= (v.z > 0.0f ? 1u : 0u) << j;
                b3 |= (v.w > 0.0f ? 1u : 0u) << j;
            }
        }
        unsigned char* gb = (unsigned char*)g_posb;
        const int off = w * 4 + qq;
        gb[(size_t)(d0 + 0) * (PWP * 4) + off] = (unsigned char)b0;
        gb[(size_t)(d0 + 1) * (PWP * 4) + off] = (unsigned char)b1;
        gb[(size_t)(d0 + 2) * (PWP * 4) + off] = (unsigned char)b2;
        gb[(size_t)(d0 + 3) * (PWP * 4) + off] = (unsigned char)b3;
    }
    if (w == 0 && qq == 0) {     // zero output once (stream-ordered before hdc)
        for (int i = tid; i < NBATCH * NCLS; i += 256) out[i] = 0.0f;
    }
}

// ---------------- kernel A2: batch-invariant prep (tpos + signatures) ----
// Runs after pack (stream order). One thread per dim pair.
__global__ __launch_bounds__(256) void prep2_kernel(const float* __restrict__ vt) {
    int i = blockIdx.x * 256 + threadIdx.x;   // pair index 0..499
    if (i >= 500) return;
    int t[2], s[2];
#pragma unroll
    for (int j = 0; j < 2; j++) {
        int d = 2 * i + j;
        const uint4* p4 = (const uint4*)&g_posb[d * PWP];
        uint4 A = p4[0], B = p4[1], C = p4[2], D = p4[3], E = p4[4], F = p4[5];
        uint32_t P = g_posb[d * PWP + 24];
        int tot = __popc(A.x) + __popc(A.y) + __popc(A.z) + __popc(A.w)
                + __popc(B.x) + __popc(B.y) + __popc(B.z) + __popc(B.w)
                + __popc(C.x) + __popc(C.y) + __popc(C.z) + __popc(C.w)
                + __popc(D.x) + __popc(D.y) + __popc(D.z) + __popc(D.w)
                + __popc(E.x) + __popc(E.y) + __popc(E.z) + __popc(E.w)
                + __popc(F.x) + __popc(F.y) + __popc(F.z) + __popc(F.w)
                + __popc(P);
        t[j] = 2 * tot - NPIX;
        uint32_t sig = 0;
#pragma unroll
        for (int l = 0; l < NLEV; l++)
            sig |= (vt[l * DIMS + d] > 0.0f ? 1u : 0u) << l;
        s[j] = (int)sig;
    }
    g_sigp[i]  = (uint32_t)s[0] | ((uint32_t)s[1] << 16);
    g_tposp[i] = ((uint32_t)t[0] & 0xFFFFu) | ((uint32_t)t[1] << 16);
}

// ---------------- kernel B: 512 CTAs = (batch, dim-half) ----------------
// 2 dims/thread (named regs), match_any level classification, 2x table
// redundancy, partial GEMV via atomicAdd (2 adds/elem: deterministic).
__global__ __launch_bounds__(256, 3) void hdc_kernel(const float* __restrict__ x,
                                                     const float* __restrict__ W,
                                                     float* __restrict__ out) {
    __shared__ uint32_t MunT[2][PW][32];   // [half][word][sg]  6.4KB
    __shared__ int      Cun[2][32];
    __shared__ uint32_t mask[NLEV][PW];
    __shared__ int      cnt[NLEV];
    __shared__ uint32_t e0w[8], e1w[8];

    const int b    = blockIdx.x;           // batch
    const int dg   = blockIdx.y;           // dim half 0..1
    const int tid  = threadIdx.x;
    const int lane = tid & 31;
    const int warp = tid >> 5;
    const bool hasd = (tid < 250);
    const int i    = dg * 250 + tid;       // dim-pair index

    // ---- hoisted global loads ----
    uint4 A0={0,0,0,0},B0={0,0,0,0},C0={0,0,0,0},D0={0,0,0,0},E0={0,0,0,0},F0={0,0,0,0};
    uint4 A1={0,0,0,0},B1={0,0,0,0},C1={0,0,0,0},D1={0,0,0,0},E1={0,0,0,0},F1={0,0,0,0};
    uint32_t P0 = 0, P1 = 0, sp = 0, tp = 0;
    if (hasd) {
        const uint4* q0 = (const uint4*)&g_posb[(2 * i + 0) * PWP];
        const uint4* q1 = (const uint4*)&g_posb[(2 * i + 1) * PWP];
        A0=q0[0]; B0=q0[1]; C0=q0[2]; D0=q0[3]; E0=q0[4]; F0=q0[5];
        A1=q1[0]; B1=q1[1]; C1=q1[2]; D1=q1[3]; E1=q1[4]; F1=q1[5];
        P0 = g_posb[(2 * i + 0) * PWP + 24];
        P1 = g_posb[(2 * i + 1) * PWP + 24];
        sp = g_sigp[i];
        tp = g_tposp[i];
    }
    const float* xb = x + b * NPIX;
    float xv[4];
#pragma unroll
    for (int r = 0; r < 4; r++) {
        int p = r * 256 + tid;
        xv[r] = (p < NPIX) ? xb[p] : -1.0f;
    }

    // ---- zero level masks (match_any writes only present levels) ----
    if (tid < NLEV * PW) ((uint32_t*)mask)[tid] = 0u;
    __syncthreads();

    // ---- phase 1: level masks via match_any (1 op vs 10 ballots) ----
#pragma unroll
    for (int r = 0; r < 4; r++) {
        int p = r * 256 + tid;
        int lvl = -1;
        if (p < NPIX) {
            int q = (int)rintf(xv[r] * 9.0f);     // round-half-even == jnp.round
            q = q < 0 ? 0 : (q > 9 ? 9 : q);
            lvl = q;
        }
        unsigned m = __match_any_sync(0xffffffffu, lvl);
        int leader = __ffs(m) - 1;
        if (lane == leader && lvl >= 0) mask[lvl][r * 8 + warp] = m;
    }
    __syncthreads();

    if (tid < NLEV) {
        int c = 0;
#pragma unroll
        for (int w = 0; w < PW; w++) c += __popc(mask[tid][w]);
        cnt[tid] = c;
    }
    __syncthreads();

    // ---- phase 2: unions, 256-wide: thread = (word-group, half, sg) ----
    {
        int qg   = tid >> 6;            // 0..3
        int half = (tid >> 5) & 1;
        int sg   = tid & 31;
        int lbase = half * 5;
        uint32_t s0 = (sg & 1)  ? 0xffffffffu : 0u;
        uint32_t s1 = (sg & 2)  ? 0xffffffffu : 0u;
        uint32_t s2 = (sg & 4)  ? 0xffffffffu : 0u;
        uint32_t s3 = (sg & 8)  ? 0xffffffffu : 0u;
        uint32_t s4 = (sg & 16) ? 0xffffffffu : 0u;
        int q0 = qg * 7;
        int q1 = q0 + 7; if (q1 > PW) q1 = PW;
        for (int q = q0; q < q1; q++) {
            uint32_t m0 = mask[lbase + 0][q];
            uint32_t m1 = mask[lbase + 1][q];
            uint32_t m2 = mask[lbase + 2][q];
            uint32_t m3 = mask[lbase + 3][q];
            uint32_t m4 = mask[lbase + 4][q];
            MunT[half][q][sg] =
                (m0 & s0) | (m1 & s1) | (m2 & s2) | (m3 & s3) | (m4 & s4);
        }
        if (qg == 0) {
            int c = 0;
#pragma unroll
            for (int l = 0; l < 5; l++)
                if (sg & (1 << l)) c += cnt[lbase + l];
            Cun[half][sg] = c;
        }
    }
    __syncthreads();

    // ---- phase 3: two dims per thread ----
    bool bit0 = false, bit1 = false;
    if (hasd) {
        int sig0 = sp & 0xFFFF, sig1 = sp >> 16;
        int tp0 = (int)(short)(tp & 0xFFFFu), tp1 = (int)(short)(tp >> 16);
        {
            const int lo = sig0 & 31, hi = (sig0 >> 5) & 31;
            int acc = 0;
#define WORDOP(pw, qi) { uint32_t u = MunT[0][qi][lo] | MunT[1][qi][hi]; \
                         acc += __popc(u & (pw)); }
            WORDOP(A0.x, 0)  WORDOP(A0.y, 1)  WORDOP(A0.z, 2)  WORDOP(A0.w, 3)
            WORDOP(B0.x, 4)  WORDOP(B0.y, 5)  WORDOP(B0.z, 6)  WORDOP(B0.w, 7)
            WORDOP(C0.x, 8)  WORDOP(C0.y, 9)  WORDOP(C0.z, 10) WORDOP(C0.w, 11)
            WORDOP(D0.x, 12) WORDOP(D0.y, 13) WORDOP(D0.z, 14) WORDOP(D0.w, 15)
            WORDOP(E0.x, 16) WORDOP(E0.y, 17) WORDOP(E0.z, 18) WORDOP(E0.w, 19)
            WORDOP(F0.x, 20) WORDOP(F0.y, 21) WORDOP(F0.z, 22) WORDOP(F0.w, 23)
            WORDOP(P0, 24)
            int s = 4 * acc - 2 * (Cun[0][lo] + Cun[1][hi]) - tp0;
            bit0 = (s > 0);
        }
        {
            const int lo = sig1 & 31, hi = (sig1 >> 5) & 31;
            int acc = 0;
            WORDOP(A1.x, 0)  WORDOP(A1.y, 1)  WORDOP(A1.z, 2)  WORDOP(A1.w, 3)
            WORDOP(B1.x, 4)  WORDOP(B1.y, 5)  WORDOP(B1.z, 6)  WORDOP(B1.w, 7)
            WORDOP(C1.x, 8)  WORDOP(C1.y, 9)  WORDOP(C1.z, 10) WORDOP(C1.w, 11)
            WORDOP(D1.x, 12) WORDOP(D1.y, 13) WORDOP(D1.z, 14) WORDOP(D1.w, 15)
            WORDOP(E1.x, 16) WORDOP(E1.y, 17) WORDOP(E1.z, 18) WORDOP(E1.w, 19)
            WORDOP(F1.x, 20) WORDOP(F1.y, 21) WORDOP(F1.z, 22) WORDOP(F1.w, 23)
            WORDOP(P1, 24)
#undef WORDOP
            int s = 4 * acc - 2 * (Cun[0][lo] + Cun[1][hi]) - tp1;
            bit1 = (s > 0);
        }
    }
    unsigned e0 = __ballot_sync(0xffffffffu, bit0);
    unsigned e1 = __ballot_sync(0xffffffffu, bit1);
    if (lane == 0) { e0w[warp] = e0; e1w[warp] = e1; }
    __syncthreads();

    // ---- stage 2: partial classifier GEMV over this 500-dim half ----
#pragma unroll
    for (int cc = 0; cc < 2; cc++) {
        int c = warp + cc * 8;
        if (c < NCLS) {
            const float2* wp = (const float2*)(W + c * DIMS + dg * 500);
            float acc = 0.0f;
#pragma unroll
            for (int k = 0; k < 8; k++) {
                int t = k * 32 + lane;
                if (t < 250) {
                    uint32_t b0 = e0w[k], b1 = e1w[k];     // LDS broadcast
                    float2 wv = wp[t];                      // coalesced 8B
                    acc += ((b0 >> lane) & 1u) ? wv.x : -wv.x;
                    acc += ((b1 >> lane) & 1u) ? wv.y : -wv.y;
                }
            }
            acc += __shfl_down_sync(0xffffffffu, acc, 16);
            acc += __shfl_down_sync(0xffffffffu, acc, 8);
            acc += __shfl_down_sync(0xffffffffu, acc, 4);
            acc += __shfl_down_sync(0xffffffffu, acc, 2);
            acc += __shfl_down_sync(0xffffffffu, acc, 1);
            if (lane == 0) atomicAdd(&out[b * NCLS + c], acc);  // 2 adds/elem
        }
    }
}

// ---------------- launch ----------------
extern "C" void kernel_launch(void* const* d_in, const int* in_sizes, int n_in,
                              void* d_out, int out_size) {
    const float* x        = (const float*)d_in[0];   // [256, 28, 28]
    const float* position = (const float*)d_in[1];   // [784, 1000]
    const float* vt       = (const float*)d_in[2];   // [10, 1000]
    const float* W        = (const float*)d_in[3];   // [10, 1000]
    float* out = (float*)d_out;                      // [256, 10]

    pack_kernel<<<dim3(25, 4), 256>>>(position, out);
    prep2_kernel<<<2, 256>>>(vt);
    hdc_kernel<<<dim3(256, 2), 256>>>(x, W, out);
}